// round 3
// baseline (speedup 1.0000x reference)
#include <cuda_runtime.h>
#include <cuda_bf16.h>
#include <cstddef>

// Problem constants (shapes confirmed against reference: D=64, B=4096, L=200)
#define DK 64
#define B_MAX 4096

// Scratch (no cudaMalloc allowed)
__device__ float  g_G1[DK * DK];       // item_W^T item_W
__device__ float  g_G2[DK * DK];       // u_emb^T u_emb
__device__ float  g_wu[B_MAX * DK];    // u_emb[b,d] * h[d]
__device__ double g_pos;               // pos_data_loss accumulator

// ---------------------------------------------------------------------------
__global__ void k_init() {
    int i = blockIdx.x * blockDim.x + threadIdx.x;
    if (i < DK * DK) { g_G1[i] = 0.f; g_G2[i] = 0.f; }
    if (i == 0) g_pos = 0.0;
}

// ---------------------------------------------------------------------------
// Gather user rows, write wu = u_emb * h, accumulate user Gram (G2).
// One block = 128 users, 256 threads, 4x4 register tile per thread.
__global__ void k_user(const int* __restrict__ uids,
                       const float* __restrict__ userW,
                       const float* __restrict__ h, int B) {
    __shared__ float su[128 * DK];
    __shared__ float sh[DK];
    const int tid  = threadIdx.x;
    const int base = blockIdx.x * 128;

    if (tid < DK) sh[tid] = h[tid];
    for (int idx = tid; idx < 128 * DK; idx += 256) {
        int r = idx >> 6, c = idx & 63;
        int u = base + r;
        su[idx] = (u < B) ? userW[(size_t)uids[u] * DK + c] : 0.f;
    }
    __syncthreads();

    // wu = u * h
    for (int idx = tid; idx < 128 * DK; idx += 256) {
        int u = base + (idx >> 6);
        if (u < B) g_wu[(size_t)u * DK + (idx & 63)] = su[idx] * sh[idx & 63];
    }

    // 4x4 register-tiled Gram over 128 rows
    const int ti = tid >> 4, tj = tid & 15;
    float acc[4][4];
#pragma unroll
    for (int a = 0; a < 4; a++)
#pragma unroll
        for (int b = 0; b < 4; b++) acc[a][b] = 0.f;

    for (int r = 0; r < 128; r++) {
        float4 vi = *(const float4*)&su[r * DK + ti * 4];
        float4 vj = *(const float4*)&su[r * DK + tj * 4];
        float ai[4] = {vi.x, vi.y, vi.z, vi.w};
        float aj[4] = {vj.x, vj.y, vj.z, vj.w};
#pragma unroll
        for (int a = 0; a < 4; a++)
#pragma unroll
            for (int b = 0; b < 4; b++) acc[a][b] += ai[a] * aj[b];
    }
#pragma unroll
    for (int a = 0; a < 4; a++)
#pragma unroll
        for (int b = 0; b < 4; b++)
            atomicAdd(&g_G2[(ti * 4 + a) * DK + tj * 4 + b], acc[a][b]);
}

// ---------------------------------------------------------------------------
// Item Gram (G1) over R rows, streamed in 64-row SMEM tiles, grid-stride.
__global__ void k_item(const float* __restrict__ itemW, int R) {
    __shared__ float si[64 * DK];
    const int tid = threadIdx.x;
    const int ti = tid >> 4, tj = tid & 15;
    float acc[4][4];
#pragma unroll
    for (int a = 0; a < 4; a++)
#pragma unroll
        for (int b = 0; b < 4; b++) acc[a][b] = 0.f;

    const int n_tiles = (R + 63) / 64;
    for (int t = blockIdx.x; t < n_tiles; t += gridDim.x) {
        const int row0  = t * 64;
        const int valid = min(64, R - row0);
        __syncthreads();  // previous tile fully consumed
        const float4* src = (const float4*)(itemW + (size_t)row0 * DK);
        float4* dst = (float4*)si;
        const int n4 = valid * (DK / 4);
        for (int i = tid; i < n4; i += 256) dst[i] = src[i];
        __syncthreads();

        for (int r = 0; r < valid; r++) {
            float4 vi = *(const float4*)&si[r * DK + ti * 4];
            float4 vj = *(const float4*)&si[r * DK + tj * 4];
            float ai[4] = {vi.x, vi.y, vi.z, vi.w};
            float aj[4] = {vj.x, vj.y, vj.z, vj.w};
#pragma unroll
            for (int a = 0; a < 4; a++)
#pragma unroll
                for (int b = 0; b < 4; b++) acc[a][b] += ai[a] * aj[b];
        }
    }
#pragma unroll
    for (int a = 0; a < 4; a++)
#pragma unroll
        for (int b = 0; b < 4; b++)
            atomicAdd(&g_G1[(ti * 4 + a) * DK + tj * 4 + b], acc[a][b]);
}

// ---------------------------------------------------------------------------
// pos_data_loss: one block per b; 8 warps split the L items; float2 dot +
// warp xor-reduce; per-block partial -> double atomic.
__global__ void k_hpq(const int* __restrict__ pos_iids,
                      const float* __restrict__ itemW,
                      int L, int PAD) {
    const int b = blockIdx.x;
    __shared__ float swu[DK];
    __shared__ float warp_s[8];
    const int tid = threadIdx.x, lane = tid & 31, wid = tid >> 5;

    if (tid < DK) swu[tid] = g_wu[(size_t)b * DK + tid];
    __syncthreads();

    const float2 w2 = {swu[lane * 2], swu[lane * 2 + 1]};
    const int* ids = pos_iids + (size_t)b * L;

    float loss = 0.f;
    for (int l = wid; l < L; l += 8) {
        const int iid = ids[l];               // uniform per warp -> broadcast
        if (iid == PAD) continue;             // mask: padding contributes 0
        const float2 v = ((const float2*)(itemW + (size_t)iid * DK))[lane];
        float d = v.x * w2.x + v.y * w2.y;
#pragma unroll
        for (int off = 16; off; off >>= 1) d += __shfl_xor_sync(0xffffffffu, d, off);
        loss += 0.9f * d * d - 2.0f * d;      // (1-NEG_WEIGHT)*hpq^2 - 2*hpq
    }
    if (lane == 0) warp_s[wid] = loss;
    __syncthreads();
    if (tid == 0) {
        float s = 0.f;
#pragma unroll
        for (int w = 0; w < 8; w++) s += warp_s[w];
        atomicAdd(&g_pos, (double)s);
    }
}

// ---------------------------------------------------------------------------
__global__ void k_combine(const float* __restrict__ h, float* __restrict__ out) {
    __shared__ float red[256];
    const int tid = threadIdx.x;
    float s = 0.f;
    for (int e = tid; e < DK * DK; e += 256) {
        int i = e >> 6, j = e & 63;
        s += g_G1[e] * g_G2[e] * h[i] * h[j];
    }
    red[tid] = s;
    __syncthreads();
    for (int k = 128; k; k >>= 1) {
        if (tid < k) red[tid] += red[tid + k];
        __syncthreads();
    }
    if (tid == 0) out[0] = 0.1f * red[0] + (float)g_pos;
}

// ---------------------------------------------------------------------------
extern "C" void kernel_launch(void* const* d_in, const int* in_sizes, int n_in,
                              void* d_out, int out_size) {
    const int*   uids     = (const int*)d_in[0];
    const int*   pos_iids = (const int*)d_in[1];
    const float* user_W   = (const float*)d_in[2];
    const float* item_W   = (const float*)d_in[3];
    const float* h        = (const float*)d_in[4];
    float* out = (float*)d_out;

    const int B   = in_sizes[0];            // 4096
    const int L   = in_sizes[1] / B;        // 200
    const int R   = in_sizes[3] / DK;       // 100001 item rows
    const int PAD = R - 1;                  // padding item id

    k_init<<<16, 256>>>();
    k_user<<<(B + 127) / 128, 256>>>(uids, user_W, h, B);
    k_item<<<444, 256>>>(item_W, R);
    k_hpq<<<B, 256>>>(pos_iids, item_W, L, PAD);
    k_combine<<<1, 256>>>(h, out);
}

// round 4
// speedup vs baseline: 1.1405x; 1.1405x over previous
#include <cuda_runtime.h>
#include <cuda_bf16.h>
#include <cstddef>

#define DK 64
#define B_MAX 4096
#define NB_USER 32          // max user blocks (B_MAX/128)
#define ITEM_BLOCKS 444
#define TPB 160             // fused kernel block size (5 warps)

// Scratch (no cudaMalloc allowed)
__device__ float  g_G1[DK * DK];                 // item_W^T item_W
__device__ float  g_G2p[NB_USER][DK * DK];       // per-block user Gram partials
__device__ float  g_wu[B_MAX * DK];              // u_emb[b,d] * h[d]
__device__ double g_pos;                         // pos_data_loss accumulator

// ---------------------------------------------------------------------------
// Gather user rows, write wu = u_emb * h, per-block user Gram partial (no
// atomics). Block 0 additionally zeroes G1 and g_pos for the next launch.
__global__ void k_user(const int* __restrict__ uids,
                       const float* __restrict__ userW,
                       const float* __restrict__ h, int B) {
    __shared__ float su[128 * DK];
    __shared__ float sh[DK];
    const int tid  = threadIdx.x;
    const int base = blockIdx.x * 128;

    if (blockIdx.x == 0) {
        for (int i = tid; i < DK * DK; i += 256) g_G1[i] = 0.f;
        if (tid == 0) g_pos = 0.0;
    }
    if (tid < DK) sh[tid] = h[tid];
    for (int idx = tid; idx < 128 * DK; idx += 256) {
        int u = base + (idx >> 6);
        su[idx] = (u < B) ? userW[(size_t)uids[u] * DK + (idx & 63)] : 0.f;
    }
    __syncthreads();

    for (int idx = tid; idx < 128 * DK; idx += 256) {
        int u = base + (idx >> 6);
        if (u < B) g_wu[(size_t)u * DK + (idx & 63)] = su[idx] * sh[idx & 63];
    }

    const int ti = tid >> 4, tj = tid & 15;
    float acc[4][4];
#pragma unroll
    for (int a = 0; a < 4; a++)
#pragma unroll
        for (int b = 0; b < 4; b++) acc[a][b] = 0.f;

    for (int r = 0; r < 128; r++) {
        float4 vi = *(const float4*)&su[r * DK + ti * 4];
        float4 vj = *(const float4*)&su[r * DK + tj * 4];
        float ai[4] = {vi.x, vi.y, vi.z, vi.w};
        float aj[4] = {vj.x, vj.y, vj.z, vj.w};
#pragma unroll
        for (int a = 0; a < 4; a++)
#pragma unroll
            for (int b = 0; b < 4; b++) acc[a][b] += ai[a] * aj[b];
    }
#pragma unroll
    for (int a = 0; a < 4; a++)
#pragma unroll
        for (int b = 0; b < 4; b++)
            g_G2p[blockIdx.x][(ti * 4 + a) * DK + tj * 4 + b] = acc[a][b];
}

// ---------------------------------------------------------------------------
// Fused: blocks [0, nItem) = item Gram (symmetric, upper-tri tiles);
//        blocks [nItem, nItem+B) = pos_data_loss (8-lane groups, 4 items/warp).
__global__ void __launch_bounds__(TPB)
k_fused(const int* __restrict__ pos_iids,
        const float* __restrict__ itemW,
        int L, int PAD, int R, int nItem) {
    __shared__ float si[64 * DK];      // 16KB item tile (hpq path reuses start)
    __shared__ float wsum[TPB / 32];
    const int tid = threadIdx.x;

    if ((int)blockIdx.x < nItem) {
        // ---- item Gram, upper triangle of 16x16 grid of 4x4 tiles ----
        int ti = 0, tj = 0;
        bool active = (tid < 136);
        if (active) {
            int k = tid, t = 0;
            while (k >= 16 - t) { k -= 16 - t; t++; }
            ti = t; tj = t + k;
        }
        float acc[4][4];
#pragma unroll
        for (int a = 0; a < 4; a++)
#pragma unroll
            for (int b = 0; b < 4; b++) acc[a][b] = 0.f;

        const int n_tiles = (R + 63) / 64;
        for (int t = blockIdx.x; t < n_tiles; t += nItem) {
            const int row0  = t * 64;
            const int valid = min(64, R - row0);
            __syncthreads();
            const float4* src = (const float4*)(itemW + (size_t)row0 * DK);
            float4* dst = (float4*)si;
            const int n4 = valid * (DK / 4);
            for (int i = tid; i < n4; i += TPB) dst[i] = src[i];
            __syncthreads();

            if (active) {
                for (int r = 0; r < valid; r++) {
                    float4 vi = *(const float4*)&si[r * DK + ti * 4];
                    float4 vj = *(const float4*)&si[r * DK + tj * 4];
                    float ai[4] = {vi.x, vi.y, vi.z, vi.w};
                    float aj[4] = {vj.x, vj.y, vj.z, vj.w};
#pragma unroll
                    for (int a = 0; a < 4; a++)
#pragma unroll
                        for (int b = 0; b < 4; b++) acc[a][b] += ai[a] * aj[b];
                }
            }
        }
        if (active) {
#pragma unroll
            for (int a = 0; a < 4; a++)
#pragma unroll
                for (int b = 0; b < 4; b++)
                    atomicAdd(&g_G1[(ti * 4 + a) * DK + tj * 4 + b], acc[a][b]);
            if (ti != tj) {
#pragma unroll
                for (int a = 0; a < 4; a++)
#pragma unroll
                    for (int b = 0; b < 4; b++)
                        atomicAdd(&g_G1[(tj * 4 + b) * DK + ti * 4 + a], acc[a][b]);
            }
        }
    } else {
        // ---- hpq: one block per batch row b ----
        const int b    = blockIdx.x - nItem;
        const int lane = tid & 31, w = tid >> 5;   // 5 warps
        const int sub  = lane & 7, grp = lane >> 3;

        if (tid < DK) si[tid] = g_wu[(size_t)b * DK + tid];
        __syncthreads();
        const float4 w0 = ((const float4*)si)[sub * 2];
        const float4 w1 = ((const float4*)si)[sub * 2 + 1];
        const int* ids = pos_iids + (size_t)b * L;

        float loss = 0.f;
        const int items_per_step = (TPB / 32) * 4;       // 20
        const int nsteps = (L + items_per_step - 1) / items_per_step;
        for (int s = 0; s < nsteps; s++) {
            const int l = s * items_per_step + w * 4 + grp;
            const int iid = (l < L) ? ids[l] : PAD;      // PAD row is valid memory
            const float4* row = (const float4*)(itemW + (size_t)iid * DK);
            float4 v0 = row[sub * 2];
            float4 v1 = row[sub * 2 + 1];
            float d = v0.x * w0.x + v0.y * w0.y + v0.z * w0.z + v0.w * w0.w
                    + v1.x * w1.x + v1.y * w1.y + v1.z * w1.z + v1.w * w1.w;
            d += __shfl_xor_sync(0xffffffffu, d, 4);
            d += __shfl_xor_sync(0xffffffffu, d, 2);
            d += __shfl_xor_sync(0xffffffffu, d, 1);
            if (sub == 0 && l < L && iid != PAD)
                loss += 0.9f * d * d - 2.0f * d;         // (1-NW)*hpq^2 - 2*hpq
        }
#pragma unroll
        for (int off = 16; off; off >>= 1)
            loss += __shfl_xor_sync(0xffffffffu, loss, off);
        if (lane == 0) wsum[w] = loss;
        __syncthreads();
        if (tid == 0) {
            float s = 0.f;
#pragma unroll
            for (int k = 0; k < TPB / 32; k++) s += wsum[k];
            atomicAdd(&g_pos, (double)s);
        }
    }
}

// ---------------------------------------------------------------------------
__global__ void k_combine(const float* __restrict__ h, float* __restrict__ out,
                          int nb) {
    __shared__ float red[256];
    const int tid = threadIdx.x;
    float s = 0.f;
    for (int e = tid; e < DK * DK; e += 256) {
        float g2 = 0.f;
        for (int p = 0; p < nb; p++) g2 += g_G2p[p][e];
        s += g_G1[e] * g2 * h[e >> 6] * h[e & 63];
    }
    red[tid] = s;
    __syncthreads();
    for (int k = 128; k; k >>= 1) {
        if (tid < k) red[tid] += red[tid + k];
        __syncthreads();
    }
    if (tid == 0) out[0] = 0.1f * red[0] + (float)g_pos;
}

// ---------------------------------------------------------------------------
extern "C" void kernel_launch(void* const* d_in, const int* in_sizes, int n_in,
                              void* d_out, int out_size) {
    const int*   uids     = (const int*)d_in[0];
    const int*   pos_iids = (const int*)d_in[1];
    const float* user_W   = (const float*)d_in[2];
    const float* item_W   = (const float*)d_in[3];
    const float* h        = (const float*)d_in[4];
    float* out = (float*)d_out;

    const int B   = in_sizes[0];          // 4096
    const int L   = in_sizes[1] / B;      // 200
    const int R   = in_sizes[3] / DK;     // 100001 item rows
    const int PAD = R - 1;                // padding item id
    const int nb  = (B + 127) / 128;      // <= 32

    k_user<<<nb, 256>>>(uids, user_W, h, B);
    k_fused<<<ITEM_BLOCKS + B, TPB>>>(pos_iids, item_W, L, PAD, R, ITEM_BLOCKS);
    k_combine<<<1, 256>>>(h, out, nb);
}

// round 5
// speedup vs baseline: 1.6330x; 1.4318x over previous
#include <cuda_runtime.h>
#include <cuda_bf16.h>
#include <cstddef>

#define DK 64
#define TPB 160             // 5 warps
#define ITEM_BLOCKS 444
#define B_MAX 4096

// Scratch (no cudaMalloc allowed)
__device__ float g_G1[DK * DK];     // item_W^T item_W   (atomic)
__device__ float g_G2[DK * DK];     // u_emb^T u_emb     (atomic)
__device__ float g_posp[B_MAX];     // per-row pos-loss partials

// ---------------------------------------------------------------------------
__global__ void k_init() {
    int i = blockIdx.x * 256 + threadIdx.x;
    if (i < DK * DK) { g_G1[i] = 0.f; g_G2[i] = 0.f; }
}

// ---------------------------------------------------------------------------
// One kernel, three block roles:
//   [0, ITEM_BLOCKS)                : item Gram (upper-tri 4x4 tiles, 136 thr)
//   [ITEM_BLOCKS, ITEM_BLOCKS+nG2)  : user Gram (64 gathered rows per block)
//   [ITEM_BLOCKS+nG2, ... + B)      : pos_data_loss, one block per batch row
__global__ void __launch_bounds__(TPB)
k_fused(const int* __restrict__ uids,
        const int* __restrict__ pos_iids,
        const float* __restrict__ userW,
        const float* __restrict__ itemW,
        const float* __restrict__ h,
        int B, int L, int PAD, int R, int nG2) {
    __shared__ float sm[64 * DK];       // 16 KB tile / wu scratch
    __shared__ float wsum[TPB / 32];
    const int tid = threadIdx.x;
    const int bid = blockIdx.x;

    if (bid < ITEM_BLOCKS + nG2) {
        // ------------------ Gram path (item or user) ------------------
        const bool isItem = bid < ITEM_BLOCKS;
        int ti = 0, tj = 0;
        const bool active = tid < 136;
        if (active) {                       // upper-tri tile map
            int k = tid, t = 0;
            while (k >= 16 - t) { k -= 16 - t; t++; }
            ti = t; tj = t + k;
        }
        float acc[4][4];
#pragma unroll
        for (int a = 0; a < 4; a++)
#pragma unroll
            for (int b = 0; b < 4; b++) acc[a][b] = 0.f;

        if (isItem) {
            const int n_tiles = (R + 63) / 64;
            for (int t = bid; t < n_tiles; t += ITEM_BLOCKS) {
                const int row0  = t * 64;
                const int valid = min(64, R - row0);
                __syncthreads();
                const float4* src = (const float4*)(itemW + (size_t)row0 * DK);
                float4* dst = (float4*)sm;
                for (int i = tid; i < valid * (DK / 4); i += TPB) dst[i] = src[i];
                __syncthreads();
                if (active) {
                    for (int r = 0; r < valid; r++) {
                        float4 vi = *(const float4*)&sm[r * DK + ti * 4];
                        float4 vj = *(const float4*)&sm[r * DK + tj * 4];
                        float ai[4] = {vi.x, vi.y, vi.z, vi.w};
                        float aj[4] = {vj.x, vj.y, vj.z, vj.w};
#pragma unroll
                        for (int a = 0; a < 4; a++)
#pragma unroll
                            for (int b = 0; b < 4; b++) acc[a][b] += ai[a] * aj[b];
                    }
                }
            }
        } else {
            const int base = (bid - ITEM_BLOCKS) * 64;
            for (int i = tid; i < 64 * DK; i += TPB) {
                int u = base + (i >> 6);
                sm[i] = (u < B) ? userW[(size_t)uids[u] * DK + (i & 63)] : 0.f;
            }
            __syncthreads();
            if (active) {
                for (int r = 0; r < 64; r++) {
                    float4 vi = *(const float4*)&sm[r * DK + ti * 4];
                    float4 vj = *(const float4*)&sm[r * DK + tj * 4];
                    float ai[4] = {vi.x, vi.y, vi.z, vi.w};
                    float aj[4] = {vj.x, vj.y, vj.z, vj.w};
#pragma unroll
                    for (int a = 0; a < 4; a++)
#pragma unroll
                        for (int b = 0; b < 4; b++) acc[a][b] += ai[a] * aj[b];
                }
            }
        }
        if (active) {
            float* G = isItem ? g_G1 : g_G2;
#pragma unroll
            for (int a = 0; a < 4; a++)
#pragma unroll
                for (int b = 0; b < 4; b++)
                    atomicAdd(&G[(ti * 4 + a) * DK + tj * 4 + b], acc[a][b]);
            if (ti != tj) {
#pragma unroll
                for (int a = 0; a < 4; a++)
#pragma unroll
                    for (int b = 0; b < 4; b++)
                        atomicAdd(&G[(tj * 4 + b) * DK + ti * 4 + a], acc[a][b]);
            }
        }
    } else {
        // ------------------ hpq: one block per batch row b ------------------
        const int b    = bid - ITEM_BLOCKS - nG2;
        const int lane = tid & 31, w = tid >> 5;
        const int sub  = lane & 7, grp = lane >> 3;

        // compute wu = userW[uids[b]] * h in-block
        if (tid < DK / 4) {
            float4 hu = ((const float4*)h)[tid];
            float4 uu = ((const float4*)(userW + (size_t)uids[b] * DK))[tid];
            float4 r;
            r.x = hu.x * uu.x; r.y = hu.y * uu.y;
            r.z = hu.z * uu.z; r.w = hu.w * uu.w;
            ((float4*)sm)[tid] = r;
        }
        __syncthreads();

        const float4 w0 = ((const float4*)sm)[sub];        // line-0 half
        const float4 w1 = ((const float4*)sm)[sub + 8];    // line-1 half
        const int* ids = pos_iids + (size_t)b * L;

        float loss = 0.f;
        const int per_step = (TPB / 32) * 8;               // 40 items/step
        const int nsteps = (L + per_step - 1) / per_step;
        for (int s = 0; s < nsteps; s++) {
            const int l1 = s * per_step + w * 8 + grp * 2;
            const int l2 = l1 + 1;
            const int i1 = (l1 < L) ? ids[l1] : PAD;
            const int i2 = (l2 < L) ? ids[l2] : PAD;
            const float4* r1 = (const float4*)(itemW + (size_t)i1 * DK);
            const float4* r2 = (const float4*)(itemW + (size_t)i2 * DK);
            float4 a0 = r1[sub], a1 = r1[sub + 8];          // 4 indep LDG.128
            float4 b0 = r2[sub], b1 = r2[sub + 8];
            float d1 = a0.x * w0.x + a0.y * w0.y + a0.z * w0.z + a0.w * w0.w
                     + a1.x * w1.x + a1.y * w1.y + a1.z * w1.z + a1.w * w1.w;
            float d2 = b0.x * w0.x + b0.y * w0.y + b0.z * w0.z + b0.w * w0.w
                     + b1.x * w1.x + b1.y * w1.y + b1.z * w1.z + b1.w * w1.w;
            d1 += __shfl_xor_sync(0xffffffffu, d1, 4);
            d2 += __shfl_xor_sync(0xffffffffu, d2, 4);
            d1 += __shfl_xor_sync(0xffffffffu, d1, 2);
            d2 += __shfl_xor_sync(0xffffffffu, d2, 2);
            d1 += __shfl_xor_sync(0xffffffffu, d1, 1);
            d2 += __shfl_xor_sync(0xffffffffu, d2, 1);
            if (sub == 0) {
                if (l1 < L && i1 != PAD) loss += 0.9f * d1 * d1 - 2.0f * d1;
                if (l2 < L && i2 != PAD) loss += 0.9f * d2 * d2 - 2.0f * d2;
            }
        }
#pragma unroll
        for (int off = 16; off; off >>= 1)
            loss += __shfl_xor_sync(0xffffffffu, loss, off);
        if (lane == 0) wsum[w] = loss;
        __syncthreads();
        if (tid == 0) {
            float s = 0.f;
#pragma unroll
            for (int k = 0; k < TPB / 32; k++) s += wsum[k];
            g_posp[b] = s;                                 // no atomic
        }
    }
}

// ---------------------------------------------------------------------------
__global__ void k_combine(const float* __restrict__ h, float* __restrict__ out,
                          int B) {
    __shared__ double red[256];
    const int tid = threadIdx.x;
    double s = 0.0;
    for (int e = tid; e < DK * DK; e += 256)
        s += (double)(g_G1[e] * g_G2[e] * h[e >> 6] * h[e & 63]) * 0.1;
    for (int i = tid; i < B; i += 256)
        s += (double)g_posp[i];
    red[tid] = s;
    __syncthreads();
    for (int k = 128; k; k >>= 1) {
        if (tid < k) red[tid] += red[tid + k];
        __syncthreads();
    }
    if (tid == 0) out[0] = (float)red[0];
}

// ---------------------------------------------------------------------------
extern "C" void kernel_launch(void* const* d_in, const int* in_sizes, int n_in,
                              void* d_out, int out_size) {
    const int*   uids     = (const int*)d_in[0];
    const int*   pos_iids = (const int*)d_in[1];
    const float* user_W   = (const float*)d_in[2];
    const float* item_W   = (const float*)d_in[3];
    const float* h        = (const float*)d_in[4];
    float* out = (float*)d_out;

    const int B   = in_sizes[0];          // 4096
    const int L   = in_sizes[1] / B;      // 200
    const int R   = in_sizes[3] / DK;     // 100001 item rows
    const int PAD = R - 1;                // padding item id
    const int nG2 = (B + 63) / 64;        // user-gram blocks

    k_init<<<16, 256>>>();
    k_fused<<<ITEM_BLOCKS + nG2 + B, TPB>>>(uids, pos_iids, user_W, item_W, h,
                                            B, L, PAD, R, nG2);
    k_combine<<<1, 256>>>(h, out, B);
}